// round 2
// baseline (speedup 1.0000x reference)
#include <cuda_runtime.h>
#include <cstdint>

#define HH 8
#define BB 8
#define SS 4096
#define DD 64
#define DMOUT 768
#define SM1 (SS-2)            // 4094
#define NKROWS (BB*SM1)       // 32752
#define KTOT (HH*DD)          // 512

// ---------------- scratch (no allocs allowed) ----------------
static __device__ float dG[HH*DD*DD];     // Gram of normalized Q
static __device__ float dU[HH*DD*DD];     // Q^T V update
static __device__ float dNT[HH*DD*DD];    // new_trace
static __device__ float dM[KTOT*DMOUT];   // fused weight: nt @ W_out_h^T

// ---------------- helpers ----------------
__device__ __forceinline__ uint32_t f2tf(float x){
    uint32_t r; asm("cvt.rna.tf32.f32 %0, %1;" : "=r"(r) : "f"(x)); return r;
}
__device__ __forceinline__ void mma_tf32(float c[4], uint32_t a0,uint32_t a1,uint32_t a2,uint32_t a3,
                                         uint32_t b0,uint32_t b1){
    asm volatile("mma.sync.aligned.m16n8k8.row.col.f32.tf32.tf32.f32 "
        "{%0,%1,%2,%3},{%4,%5,%6,%7},{%8,%9},{%0,%1,%2,%3};"
        : "+f"(c[0]),"+f"(c[1]),"+f"(c[2]),"+f"(c[3])
        : "r"(a0),"r"(a1),"r"(a2),"r"(a3),"r"(b0),"r"(b1));
}

// ---------------- kernel 0: zero scratch ----------------
__global__ void k_zero(){
    int i = blockIdx.x*256 + threadIdx.x;   // 128 blocks -> 32768
    dG[i] = 0.f; dU[i] = 0.f;
}

// ---------------- kernel 1: G[h] = Qe^T Qe, U[h] = Q^T V ----------------
// grid (32 chunks, 8 heads), 128 threads (4 warps). Each warp owns 16 M-rows x 64 N.
__global__ void __launch_bounds__(128) k_stage1(const float* __restrict__ Q,
                                                const float* __restrict__ V){
    const int h    = blockIdx.y;
    const int row0 = blockIdx.x * 1024;
    const int tid  = threadIdx.x;
    const int warp = tid >> 5, lane = tid & 31;
    const int grp  = lane >> 2, tg = lane & 3;

    __shared__ float sQ[32][72];   // stride 72 -> conflict-free frag loads
    __shared__ float sV[32][72];
    __shared__ float sInv[32];     // 1/max(||q||,eps)^2 per row

    float accG[8][4], accU[8][4];
    #pragma unroll
    for(int i=0;i<8;i++){
        #pragma unroll
        for(int j=0;j<4;j++){ accG[i][j]=0.f; accU[i][j]=0.f; }
    }
    const int m0 = warp*16 + grp;

    for(int kt=0; kt<32; kt++){
        const int base = row0 + kt*32;
        // load 32 rows of Q (key at i) and V (value at i+2)
        #pragma unroll
        for(int j=0;j<4;j++){
            int f4  = tid + j*128;           // 0..511
            int row = f4 >> 4, c4 = f4 & 15;
            int gr  = base + row;
            float4 q = make_float4(0.f,0.f,0.f,0.f);
            float4 v = make_float4(0.f,0.f,0.f,0.f);
            if(gr < NKROWS){
                int b = gr / SM1;
                int i = gr - b*SM1;
                size_t qoff = (((size_t)(b*HH + h))*SS + i)*DD;
                size_t voff = (((size_t)(b*HH + h))*SS + i + 2)*DD;
                q = *((const float4*)(Q + qoff) + c4);
                v = *((const float4*)(V + voff) + c4);
            }
            *(float4*)&sQ[row][c4*4] = q;
            *(float4*)&sV[row][c4*4] = v;
        }
        __syncthreads();
        if(tid < 32){
            float s = 0.f;
            #pragma unroll
            for(int d=0; d<64; d++){ float x = sQ[tid][d]; s += x*x; }
            float nrm = fmaxf(sqrtf(s), 1e-8f);
            sInv[tid] = 1.f/(nrm*nrm);
        }
        __syncthreads();

        #pragma unroll
        for(int ks=0; ks<4; ks++){
            const int kA = ks*8 + tg;
            float ar0 = sQ[kA  ][m0  ], ar1 = sQ[kA  ][m0+8];
            float ar2 = sQ[kA+4][m0  ], ar3 = sQ[kA+4][m0+8];
            float i0 = sInv[kA], i1 = sInv[kA+4];
            uint32_t aU0=f2tf(ar0),    aU1=f2tf(ar1),    aU2=f2tf(ar2),    aU3=f2tf(ar3);
            uint32_t aG0=f2tf(ar0*i0), aG1=f2tf(ar1*i0), aG2=f2tf(ar2*i1), aG3=f2tf(ar3*i1);
            #pragma unroll
            for(int nt=0; nt<8; nt++){
                const int n = nt*8 + grp;
                uint32_t bq0 = f2tf(sQ[kA  ][n]);
                uint32_t bq1 = f2tf(sQ[kA+4][n]);
                uint32_t bv0 = f2tf(sV[kA  ][n]);
                uint32_t bv1 = f2tf(sV[kA+4][n]);
                mma_tf32(accG[nt], aG0,aG1,aG2,aG3, bq0,bq1);
                mma_tf32(accU[nt], aU0,aU1,aU2,aU3, bv0,bv1);
            }
        }
        __syncthreads();
    }
    // reduce partials into global scratch
    #pragma unroll
    for(int nt=0; nt<8; nt++){
        const int n = nt*8 + tg*2;
        int baseIdx = h*4096;
        atomicAdd(&dG[baseIdx + (m0  )*64 + n  ], accG[nt][0]);
        atomicAdd(&dG[baseIdx + (m0  )*64 + n+1], accG[nt][1]);
        atomicAdd(&dG[baseIdx + (m0+8)*64 + n  ], accG[nt][2]);
        atomicAdd(&dG[baseIdx + (m0+8)*64 + n+1], accG[nt][3]);
        atomicAdd(&dU[baseIdx + (m0  )*64 + n  ], accU[nt][0]);
        atomicAdd(&dU[baseIdx + (m0  )*64 + n+1], accU[nt][1]);
        atomicAdd(&dU[baseIdx + (m0+8)*64 + n  ], accU[nt][2]);
        atomicAdd(&dU[baseIdx + (m0+8)*64 + n+1], accU[nt][3]);
    }
}

// ---------------- kernel 2: new_trace = 0.99*(trace - G@trace/denom) + 0.1*U/denom ----------------
__global__ void __launch_bounds__(256) k_trace(const float* __restrict__ trace){
    const int h = blockIdx.x, tid = threadIdx.x;
    __shared__ float sT[4096], sG[4096];
    #pragma unroll
    for(int t=0;t<16;t++){ int i = tid + t*256; sT[i] = trace[h*4096 + i]; sG[i] = dG[h*4096 + i]; }
    __syncthreads();
    const float inv = 1.f/(float)NKROWS;
    #pragma unroll
    for(int t=0;t<16;t++){
        int i = tid + t*256;
        int p = i >> 6, q = i & 63;
        float gt = 0.f;
        #pragma unroll
        for(int r=0;r<64;r++) gt += sG[p*64 + r]*sT[r*64 + q];
        dNT[h*4096 + i] = 0.99f*(sT[i] - gt*inv) + 0.1f*dU[h*4096 + i]*inv;
    }
}

// ---------------- kernel 3: M[h*64+p][dm] = sum_q nt[h][p][q] * W_out[dm][h*64+q] ----------------
__global__ void __launch_bounds__(128) k_makeM(const float* __restrict__ Wout){
    const int h = blockIdx.y;
    const int dm0 = blockIdx.x * 64;
    const int tid = threadIdx.x;
    __shared__ float sNT[4096];
    __shared__ float sW[64][65];
    #pragma unroll
    for(int t=0;t<32;t++){ int i = tid + t*128; sNT[i] = dNT[h*4096 + i]; }
    #pragma unroll
    for(int t=0;t<32;t++){
        int i = tid + t*128; int r = i >> 6, q = i & 63;
        sW[r][q] = Wout[(size_t)(dm0 + r)*KTOT + h*64 + q];
    }
    __syncthreads();
    #pragma unroll
    for(int t=0;t<32;t++){
        int i = tid + t*128; int p = i >> 6, dm = i & 63;
        float s = 0.f;
        #pragma unroll
        for(int q=0;q<64;q++) s += sNT[p*64 + q]*sW[dm][q];
        dM[(size_t)(h*64 + p)*DMOUT + dm0 + dm] = s;
    }
}

// ---------------- kernel 4: fused out = X @ M,  X[b*S+s][h*64+d] = Q[b,h,s-1,d] (0 at s=0) ----------------
// grid (6 n-tiles, 256 m-tiles), 256 threads = 8 warps (2M x 4N), warp tile 64x32, BK=32.
// Software-pipelined: next k-tile's global loads prefetched into registers
// before the MMA loop of the current tile.
__global__ void __launch_bounds__(256) k_gemm(const float* __restrict__ Q,
                                              float* __restrict__ out){
    const int nblk = blockIdx.x;
    const int mblk = blockIdx.y;
    const int tid  = threadIdx.x;
    const int warp = tid >> 5, lane = tid & 31;
    const int grp  = lane >> 2, tg = lane & 3;
    const int warpM = warp >> 2, warpN = warp & 3;

    __shared__ float sA[128*36];   // [m][k], stride 36
    __shared__ float sB[32*136];   // [k][n], stride 136

    float acc[4][4][4];
    #pragma unroll
    for(int mi=0;mi<4;mi++)
        #pragma unroll
        for(int ni=0;ni<4;ni++)
            #pragma unroll
            for(int f=0;f<4;f++) acc[mi][ni][f] = 0.f;

    const int r0  = mblk*128;
    const int b   = r0 >> 12;       // /4096, tiles never straddle a batch
    const int s0  = r0 & 4095;
    const int n0g = nblk*128;

    // per-thread loader coordinates (constant across k-tiles)
    int arow[4], ac4[4], brow[4], bc4[4];
    #pragma unroll
    for(int j=0;j<4;j++){
        int f4 = tid + j*256;
        arow[j] = f4 >> 3; ac4[j] = f4 & 7;    // A: 128 rows x 8 float4
        brow[j] = f4 >> 5; bc4[j] = f4 & 31;   // B: 32 rows x 32 float4
    }

    float4 pa[4], pb[4];
    // prefetch k-tile 0
    {
        const int k0 = 0, hh = 0, d0 = 0;
        const float* Qbase = Q + ((size_t)(b*HH + hh))*SS*DD;
        #pragma unroll
        for(int j=0;j<4;j++){
            int s = s0 + arow[j];
            pa[j] = make_float4(0.f,0.f,0.f,0.f);
            if(s > 0)
                pa[j] = *((const float4*)(Qbase + (size_t)(s-1)*DD + d0) + ac4[j]);
            pb[j] = *((const float4*)(dM + (size_t)(k0 + brow[j])*DMOUT + n0g) + bc4[j]);
        }
    }

    for(int kb=0; kb<16; kb++){
        // store prefetched tile to smem with tf32 conversion
        #pragma unroll
        for(int j=0;j<4;j++){
            float4 v = pa[j];
            v.x = __uint_as_float(f2tf(v.x));
            v.y = __uint_as_float(f2tf(v.y));
            v.z = __uint_as_float(f2tf(v.z));
            v.w = __uint_as_float(f2tf(v.w));
            *(float4*)&sA[arow[j]*36 + ac4[j]*4] = v;
            float4 w = pb[j];
            w.x = __uint_as_float(f2tf(w.x));
            w.y = __uint_as_float(f2tf(w.y));
            w.z = __uint_as_float(f2tf(w.z));
            w.w = __uint_as_float(f2tf(w.w));
            *(float4*)&sB[brow[j]*136 + bc4[j]*4] = w;
        }
        __syncthreads();

        // prefetch next k-tile (overlaps with MMA below)
        if(kb < 15){
            const int k0 = (kb+1)*32;
            const int hh = k0 >> 6;
            const int d0 = k0 & 63;
            const float* Qbase = Q + ((size_t)(b*HH + hh))*SS*DD;
            #pragma unroll
            for(int j=0;j<4;j++){
                int s = s0 + arow[j];
                pa[j] = make_float4(0.f,0.f,0.f,0.f);
                if(s > 0)
                    pa[j] = *((const float4*)(Qbase + (size_t)(s-1)*DD + d0) + ac4[j]);
                pb[j] = *((const float4*)(dM + (size_t)(k0 + brow[j])*DMOUT + n0g) + bc4[j]);
            }
        }

        #pragma unroll
        for(int ks=0; ks<4; ks++){
            const int kk = ks*8 + tg;
            uint32_t a[4][4];
            #pragma unroll
            for(int mi=0;mi<4;mi++){
                int m = warpM*64 + mi*16 + grp;
                a[mi][0] = __float_as_uint(sA[(m  )*36 + kk  ]);
                a[mi][1] = __float_as_uint(sA[(m+8)*36 + kk  ]);
                a[mi][2] = __float_as_uint(sA[(m  )*36 + kk+4]);
                a[mi][3] = __float_as_uint(sA[(m+8)*36 + kk+4]);
            }
            #pragma unroll
            for(int ni=0;ni<4;ni++){
                int n = warpN*32 + ni*8 + grp;
                uint32_t b0 = __float_as_uint(sB[(kk  )*136 + n]);
                uint32_t b1 = __float_as_uint(sB[(kk+4)*136 + n]);
                #pragma unroll
                for(int mi=0;mi<4;mi++)
                    mma_tf32(acc[mi][ni], a[mi][0],a[mi][1],a[mi][2],a[mi][3], b0,b1);
            }
        }
        __syncthreads();
    }

    // epilogue: rows r = b*S+s map directly to out rows
    #pragma unroll
    for(int mi=0;mi<4;mi++){
        const int m = warpM*64 + mi*16 + grp;
        const size_t r1 = (size_t)(r0 + m    )*DMOUT;
        const size_t r2 = (size_t)(r0 + m + 8)*DMOUT;
        #pragma unroll
        for(int ni=0;ni<4;ni++){
            const int n = n0g + warpN*32 + ni*8 + tg*2;
            *(float2*)&out[r1 + n] = make_float2(acc[mi][ni][0], acc[mi][ni][1]);
            *(float2*)&out[r2 + n] = make_float2(acc[mi][ni][2], acc[mi][ni][3]);
        }
    }
}

// ---------------- launch ----------------
extern "C" void kernel_launch(void* const* d_in, const int* in_sizes, int n_in,
                              void* d_out, int out_size){
    const float* Q     = (const float*)d_in[0];
    const float* V     = (const float*)d_in[1];
    const float* trace = (const float*)d_in[2];
    const float* Wout  = (const float*)d_in[3];
    float* out = (float*)d_out;

    k_zero<<<128, 256>>>();
    dim3 g1(32, HH);  k_stage1<<<g1, 128>>>(Q, V);
    k_trace<<<HH, 256>>>(trace);
    dim3 g3(12, HH);  k_makeM<<<g3, 128>>>(Wout);
    dim3 g4(6, 256);  k_gemm<<<g4, 256>>>(Q, out);
}